// round 17
// baseline (speedup 1.0000x reference)
#include <cuda_runtime.h>
#include <cuda_fp16.h>
#include <cstdint>
#include <math.h>

#define BS 4
#define LQ 12240
#define HEADS 8
#define MTOT (BS * LQ)   // 48960
#define KDIM 256

// ---------------- scratch (no cudaMalloc allowed) ----------------
__device__ __half g_v[(size_t)MTOT * 256];    // projected value, fp16
__device__ float g_off[(size_t)MTOT * 256];
__device__ float g_attn[(size_t)MTOT * 128];
__device__ float g_acc[(size_t)MTOT * 256];

// packed half2 weights: [kt 0..15][slot 0..7][n]; slot s holds (k=kt*16+2s, k+1)
__device__ uint32_t g_Wval_p[16 * 8 * 256];
__device__ uint32_t g_Woff_p[16 * 8 * 256];
__device__ uint32_t g_Wattn_p[16 * 8 * 128];
__device__ uint32_t g_Wout_p[16 * 8 * 256];

__device__ __forceinline__ void mma_f16(float* d, const uint32_t* a, const uint32_t* b) {
    asm volatile(
        "mma.sync.aligned.m16n8k16.row.col.f32.f16.f16.f32 "
        "{%0,%1,%2,%3}, {%4,%5,%6,%7}, {%8,%9}, {%0,%1,%2,%3};"
        : "+f"(d[0]), "+f"(d[1]), "+f"(d[2]), "+f"(d[3])
        : "r"(a[0]), "r"(a[1]), "r"(a[2]), "r"(a[3]), "r"(b[0]), "r"(b[1]));
}

__device__ __forceinline__ void cp_async16(void* smem, const void* gmem) {
    uint32_t s = (uint32_t)__cvta_generic_to_shared(smem);
    asm volatile("cp.async.ca.shared.global [%0], [%1], 16;" :: "r"(s), "l"(gmem));
}

__device__ __forceinline__ uint32_t pack_h2(float lo, float hi) {
    __half2 h = __floats2half2_rn(lo, hi);
    return *(uint32_t*)&h;
}

// ---------------- weight pre-pack (one launch, 4 weights) ----------------
__global__ __launch_bounds__(256) void pack_kernel(
    const float* __restrict__ Wv, const float* __restrict__ Wo,
    const float* __restrict__ Wa, const float* __restrict__ Wu,
    uint32_t* __restrict__ Pv, uint32_t* __restrict__ Po,
    uint32_t* __restrict__ Pa, uint32_t* __restrict__ Pu)
{
    const float* W; uint32_t* P; int N;
    switch (blockIdx.y) {
        case 0: W = Wv; P = Pv; N = 256; break;
        case 1: W = Wo; P = Po; N = 256; break;
        case 2: W = Wa; P = Pa; N = 128; break;
        default: W = Wu; P = Pu; N = 256; break;
    }
    const int idx = blockIdx.x * 256 + threadIdx.x;
    if (idx >= 16 * 8 * N) return;
    const int n = idx % N;
    const int s = (idx / N) & 7;
    const int kt = idx / (N * 8);
    const int k = kt * 16 + 2 * s;
    P[idx] = pack_h2(W[(size_t)k * N + n], W[(size_t)(k + 1) * N + n]);
}

#define ASTRIDE 24     // A floats per row (16 + 8 pad): LDS.64 conflict-free
#define BSTRIDE 136    // B uint per slot row (128 + 8 pad): conflict-free

#define A_STAGE (128 * ASTRIDE)
#define B_STAGE (8 * BSTRIDE)
#define SMEM_BYTES (3 * A_STAGE * 4 + 3 * B_STAGE * 4)   // 49920

// ---------------- fp16 tensor-core GEMM body ----------------
// Block tile 128x128, 8 warps 4(M) x 2(N), warp 32x64 = 2x8 m16n8k16 tiles.
// half_out: epilogue writes __half2 instead of float2.
__device__ __forceinline__ void gemm_body(
    const float* __restrict__ A, const uint32_t* __restrict__ Bp,
    const float* __restrict__ bias, void* __restrict__ Cv,
    int M, int N, int bm, int bn, int half_out)
{
    extern __shared__ char smem[];
    float (*As)[128][ASTRIDE] = (float (*)[128][ASTRIDE])smem;
    uint32_t (*Bs)[8][BSTRIDE] = (uint32_t (*)[8][BSTRIDE])(smem + 3 * A_STAGE * 4);

    const int tid = threadIdx.x;
    const int warp = tid >> 5;
    const int lane = tid & 31;
    const int wm = (warp >> 1) * 32;
    const int wn = (warp & 1) * 64;
    const int g = lane >> 2;
    const int tig = lane & 3;

    const int a_row = tid >> 1;
    const int a_half = tid & 1;
    int a_grow = bm + a_row; if (a_grow >= M) a_grow = M - 1;
    const float* Ag = A + (size_t)a_grow * KDIM + a_half * 8;

    const int b_slot = tid >> 5;
    const int b_pos = lane * 4;
    const uint32_t* Bg = Bp + (size_t)b_slot * N + bn + b_pos;

#define FILL(kt, stg) do { \
        const float* ap = Ag + (kt) * 16; \
        cp_async16(&As[stg][a_row][a_half * 8], ap); \
        cp_async16(&As[stg][a_row][a_half * 8 + 4], ap + 4); \
        cp_async16(&Bs[stg][b_slot][b_pos], Bg + (size_t)(kt) * 8 * N); \
        asm volatile("cp.async.commit_group;"); \
    } while (0)

    float acc[2][8][4];
#pragma unroll
    for (int i = 0; i < 2; i++)
#pragma unroll
        for (int j = 0; j < 8; j++)
#pragma unroll
            for (int r = 0; r < 4; r++) acc[i][j][r] = 0.f;

    const int NT = KDIM / 16;
    FILL(0, 0);
    FILL(1, 1);

    int st = 0;
    for (int kt = 0; kt < NT; kt++) {
        if (kt + 1 < NT) {
            asm volatile("cp.async.wait_group 1;");
        } else {
            asm volatile("cp.async.wait_group 0;");
        }
        __syncthreads();

        if (kt + 2 < NT) {
            int fs = st - 1; if (fs < 0) fs += 3;
            FILL(kt + 2, fs);
        }

        uint32_t af[2][4];
#pragma unroll
        for (int mt = 0; mt < 2; mt++) {
            const int mb = wm + mt * 16;
            float2 f0 = *(const float2*)&As[st][mb + g][2 * tig];
            float2 f1 = *(const float2*)&As[st][mb + g + 8][2 * tig];
            float2 f2 = *(const float2*)&As[st][mb + g][2 * tig + 8];
            float2 f3 = *(const float2*)&As[st][mb + g + 8][2 * tig + 8];
            af[mt][0] = pack_h2(f0.x, f0.y);
            af[mt][1] = pack_h2(f1.x, f1.y);
            af[mt][2] = pack_h2(f2.x, f2.y);
            af[mt][3] = pack_h2(f3.x, f3.y);
        }
        uint32_t bf[8][2];
#pragma unroll
        for (int nt = 0; nt < 8; nt++) {
            const int n = wn + nt * 8 + g;
            bf[nt][0] = Bs[st][tig][n];
            bf[nt][1] = Bs[st][tig + 4][n];
        }
#pragma unroll
        for (int mt = 0; mt < 2; mt++)
#pragma unroll
            for (int nt = 0; nt < 8; nt++)
                mma_f16(acc[mt][nt], af[mt], bf[nt]);

        st = st + 1 == 3 ? 0 : st + 1;
    }

    // epilogue
#pragma unroll
    for (int nt = 0; nt < 8; nt++) {
        const int n = bn + wn + nt * 8 + 2 * tig;
        const float b0 = bias[n];
        const float b1 = bias[n + 1];
#pragma unroll
        for (int mt = 0; mt < 2; mt++) {
            const int m0 = bm + wm + mt * 16 + g;
            const int m1 = m0 + 8;
            if (half_out) {
                __half* Ch = (__half*)Cv;
                if (m0 < M)
                    *(__half2*)&Ch[(size_t)m0 * N + n] =
                        __floats2half2_rn(acc[mt][nt][0] + b0, acc[mt][nt][1] + b1);
                if (m1 < M)
                    *(__half2*)&Ch[(size_t)m1 * N + n] =
                        __floats2half2_rn(acc[mt][nt][2] + b0, acc[mt][nt][3] + b1);
            } else {
                float* Cf = (float*)Cv;
                if (m0 < M)
                    *(float2*)&Cf[(size_t)m0 * N + n] =
                        make_float2(acc[mt][nt][0] + b0, acc[mt][nt][1] + b1);
                if (m1 < M)
                    *(float2*)&Cf[(size_t)m1 * N + n] =
                        make_float2(acc[mt][nt][2] + b0, acc[mt][nt][3] + b1);
            }
        }
    }
#undef FILL
}

// Output projection (fp32 out).
__global__ __launch_bounds__(256, 2) void gemm_f16_kernel(
    const float* __restrict__ A, const uint32_t* __restrict__ Bp,
    const float* __restrict__ bias, float* __restrict__ C, int M, int N)
{
    gemm_body(A, Bp, bias, C, M, N, blockIdx.y * 128, blockIdx.x * 128, 0);
}

// Merged projections: slots 0-1 v (half out), 2-3 off, 4 attn.
__global__ __launch_bounds__(256, 2) void proj_f16_kernel(
    const float* __restrict__ query, const float* __restrict__ value,
    const uint32_t* __restrict__ Pv, const float* __restrict__ b_val,
    const uint32_t* __restrict__ Po, const float* __restrict__ b_off,
    const uint32_t* __restrict__ Pa, const float* __restrict__ b_attn,
    __half* __restrict__ v_out, float* __restrict__ off_out,
    float* __restrict__ attn_out, int M)
{
    const int slot = blockIdx.x;
    const float *A, *bias;
    const uint32_t* Bp;
    void* C;
    int N, bn, ho;
    if (slot < 2)      { A = value; Bp = Pv; bias = b_val;  C = v_out;    N = 256; bn = slot * 128; ho = 1; }
    else if (slot < 4) { A = query; Bp = Po; bias = b_off;  C = off_out;  N = 256; bn = (slot - 2) * 128; ho = 0; }
    else               { A = query; Bp = Pa; bias = b_attn; C = attn_out; N = 128; bn = 0; ho = 0; }

    gemm_body(A, Bp, bias, C, M, N, blockIdx.y * 128, bn, ho);
}

// ---------------- softmax + bilinear sampling (v in fp16) ----------------
__global__ __launch_bounds__(256) void sample_kernel(
    const float* __restrict__ refp, const float* __restrict__ off,
    const float* __restrict__ logits, const __half* __restrict__ v,
    float* __restrict__ out)
{
    __shared__ int4   s_off[HEADS][16];
    __shared__ float4 s_w[HEADS][16];

    const int bq = blockIdx.x;
    const int b = bq / LQ;
    const int h = threadIdx.x >> 5;
    const int lane = threadIdx.x & 31;
    const int j = lane & 15;

    const float* lg = logits + (size_t)bq * 128 + h * 16;
    float logit = lg[j];
    float mx = logit;
#pragma unroll
    for (int k = 8; k >= 1; k >>= 1)
        mx = fmaxf(mx, __shfl_xor_sync(0xffffffffu, mx, k, 16));
    float e = __expf(logit - mx);
    float s = e;
#pragma unroll
    for (int k = 8; k >= 1; k >>= 1)
        s += __shfl_xor_sync(0xffffffffu, s, k, 16);
    const float aw = e / s;

    const int l = j >> 2;
    const int D = 96 >> l;
    const int start = 12288 - (12288 >> (2 * l));
    const float fD = (float)D;

    const float2 r2 = ((const float2*)(refp + (size_t)bq * 8))[l];
    const float2 o2 = ((const float2*)(off + (size_t)bq * 256 + h * 32))[j];

    const float gx = fmaf(r2.x, fD, o2.x) - 0.5f;
    const float gy = fmaf(r2.y, fD, o2.y) - 0.5f;
    const float x0f = floorf(gx);
    const float y0f = floorf(gy);
    const float wx = gx - x0f;
    const float wy = gy - y0f;
    const int x0 = (int)x0f, y0 = (int)y0f;
    const int x1 = x0 + 1, y1 = y0 + 1;

    const bool vx0 = (x0 >= 0) & (x0 < D);
    const bool vx1 = (x1 >= 0) & (x1 < D);
    const bool vy0 = (y0 >= 0) & (y0 < D);
    const bool vy1 = (y1 >= 0) & (y1 < D);

    int4 o4;
    float4 w4;
    o4.x = (vx0 & vy0) ? (start + y0 * D + x0) * 256 : 0;
    o4.y = (vx1 & vy0) ? (start + y0 * D + x1) * 256 : 0;
    o4.z = (vx0 & vy1) ? (start + y1 * D + x0) * 256 : 0;
    o4.w = (vx1 & vy1) ? (start + y1 * D + x1) * 256 : 0;
    w4.x = (vx0 & vy0) ? (1.f - wx) * (1.f - wy) * aw : 0.f;
    w4.y = (vx1 & vy0) ? wx * (1.f - wy) * aw : 0.f;
    w4.z = (vx0 & vy1) ? (1.f - wx) * wy * aw : 0.f;
    w4.w = (vx1 & vy1) ? wx * wy * aw : 0.f;

    if (lane < 16) {
        s_off[h][j] = o4;
        s_w[h][j] = w4;
    }
    __syncwarp();

    const __half* __restrict__ vb = v + (size_t)b * LQ * 256 + h * 32 + lane;
    float acc = 0.f;
#pragma unroll
    for (int p = 0; p < 16; p++) {
        const int4 o = s_off[h][p];
        const float4 w = s_w[h][p];
        acc = fmaf(w.x, __half2float(__ldg(vb + o.x)), acc);
        acc = fmaf(w.y, __half2float(__ldg(vb + o.y)), acc);
        acc = fmaf(w.z, __half2float(__ldg(vb + o.z)), acc);
        acc = fmaf(w.w, __half2float(__ldg(vb + o.w)), acc);
    }
    out[(size_t)bq * 256 + h * 32 + lane] = acc;
}

// ---------------- launch ----------------
extern "C" void kernel_launch(void* const* d_in, const int* in_sizes, int n_in,
                              void* d_out, int out_size)
{
    const float* query = (const float*)d_in[0];
    const float* refp  = (const float*)d_in[1];
    const float* value = (const float*)d_in[2];
    const float* W_off  = (const float*)d_in[4];
    const float* b_off  = (const float*)d_in[5];
    const float* W_attn = (const float*)d_in[6];
    const float* b_attn = (const float*)d_in[7];
    const float* W_val  = (const float*)d_in[8];
    const float* b_val  = (const float*)d_in[9];
    const float* W_out  = (const float*)d_in[10];
    const float* b_out  = (const float*)d_in[11];
    float* out = (float*)d_out;

    __half* pv;
    float *poff, *pattn, *pacc;
    uint32_t *pWval, *pWoff, *pWattn, *pWout;
    cudaGetSymbolAddress((void**)&pv, g_v);
    cudaGetSymbolAddress((void**)&poff, g_off);
    cudaGetSymbolAddress((void**)&pattn, g_attn);
    cudaGetSymbolAddress((void**)&pacc, g_acc);
    cudaGetSymbolAddress((void**)&pWval, g_Wval_p);
    cudaGetSymbolAddress((void**)&pWoff, g_Woff_p);
    cudaGetSymbolAddress((void**)&pWattn, g_Wattn_p);
    cudaGetSymbolAddress((void**)&pWout, g_Wout_p);

    cudaFuncSetAttribute(proj_f16_kernel, cudaFuncAttributeMaxDynamicSharedMemorySize, SMEM_BYTES);
    cudaFuncSetAttribute(gemm_f16_kernel, cudaFuncAttributeMaxDynamicSharedMemorySize, SMEM_BYTES);

    const int M = MTOT;
    dim3 blk(256);
    const int MB = (M + 127) / 128;   // 383

    pack_kernel<<<dim3(128, 4), blk>>>(W_val, W_off, W_attn, W_out,
                                       pWval, pWoff, pWattn, pWout);
    proj_f16_kernel<<<dim3(5, MB), blk, SMEM_BYTES>>>(query, value, pWval, b_val,
                                                      pWoff, b_off, pWattn, b_attn,
                                                      pv, poff, pattn, M);
    sample_kernel<<<M, blk>>>(refp, poff, pattn, pv, pacc);
    gemm_f16_kernel<<<dim3(2, MB), blk, SMEM_BYTES>>>(pacc, pWout, b_out, out, M, 256);
}